// round 1
// baseline (speedup 1.0000x reference)
#include <cuda_runtime.h>
#include <math.h>

#define BATCH 8
#define TLEN  2048
#define DDIM  512
#define BLK   64
#define KT    16
#define NTILE (TLEN / BLK)                 // 32
#define NPAIRS (NTILE * (NTILE + 1) / 2)   // 528

// reciprocal row norms: 1 / max(||x||, 1e-12)
__device__ float g_rnorm[BATCH * TLEN];

__global__ void norm_kernel(const float* __restrict__ X) {
    int row = blockIdx.x;  // 0 .. BATCH*TLEN-1
    const float4* xr = (const float4*)(X + (size_t)row * DDIM);
    float s = 0.f;
    for (int i = threadIdx.x; i < DDIM / 4; i += 128) {
        float4 v = xr[i];
        s += v.x * v.x + v.y * v.y + v.z * v.z + v.w * v.w;
    }
#pragma unroll
    for (int o = 16; o; o >>= 1) s += __shfl_xor_sync(0xffffffffu, s, o);
    __shared__ float ws[4];
    if ((threadIdx.x & 31) == 0) ws[threadIdx.x >> 5] = s;
    __syncthreads();
    if (threadIdx.x == 0) {
        float tot = ws[0] + ws[1] + ws[2] + ws[3];
        float n = fmaxf(sqrtf(tot), 1e-12f);
        g_rnorm[row] = 1.0f / n;
    }
}

// C[b] = Xn[b] * Xn[b]^T, exploiting symmetry: only tiles (i<=j) computed,
// each block writes its 64x64 tile AND the transposed tile.
__global__ void __launch_bounds__(256) gemm_kernel(const float* __restrict__ X,
                                                   float* __restrict__ out) {
    const int b   = blockIdx.y;
    const int lin = blockIdx.x;

    // decode triangular pair: lin = j*(j+1)/2 + i, i <= j
    int j = (int)((sqrtf(8.0f * (float)lin + 1.0f) - 1.0f) * 0.5f);
    while ((j + 1) * (j + 2) / 2 <= lin) j++;
    while (j * (j + 1) / 2 > lin) j--;
    const int i = lin - j * (j + 1) / 2;

    const int row0 = i * BLK;  // s-block
    const int col0 = j * BLK;  // t-block

    __shared__ float As[KT][BLK];
    __shared__ float Bs[KT][BLK];
    __shared__ float Cs[BLK][BLK + 1];  // transpose staging (padded)

    const int tid = threadIdx.x;   // 0..255
    const int tx  = tid & 15;      // t-dim
    const int ty  = tid >> 4;      // s-dim

    const float* Xb = X + (size_t)b * TLEN * DDIM;

    float acc[4][4];
#pragma unroll
    for (int u = 0; u < 4; u++)
#pragma unroll
        for (int v = 0; v < 4; v++) acc[u][v] = 0.f;

    const int lr = tid >> 2;  // 0..63 row within tile
    const int lc = tid & 3;   // 0..3  float4 slot within K-tile

    for (int k0 = 0; k0 < DDIM; k0 += KT) {
        float4 av = *(const float4*)(Xb + (size_t)(row0 + lr) * DDIM + k0 + lc * 4);
        float4 bv = *(const float4*)(Xb + (size_t)(col0 + lr) * DDIM + k0 + lc * 4);
        __syncthreads();  // protect previous iteration's smem reads
        As[lc * 4 + 0][lr] = av.x; As[lc * 4 + 1][lr] = av.y;
        As[lc * 4 + 2][lr] = av.z; As[lc * 4 + 3][lr] = av.w;
        Bs[lc * 4 + 0][lr] = bv.x; Bs[lc * 4 + 1][lr] = bv.y;
        Bs[lc * 4 + 2][lr] = bv.z; Bs[lc * 4 + 3][lr] = bv.w;
        __syncthreads();
#pragma unroll
        for (int k = 0; k < KT; k++) {
            float4 a = *(const float4*)&As[k][ty * 4];
            float4 c = *(const float4*)&Bs[k][tx * 4];
            float aa[4] = {a.x, a.y, a.z, a.w};
            float bb[4] = {c.x, c.y, c.z, c.w};
#pragma unroll
            for (int u = 0; u < 4; u++)
#pragma unroll
                for (int v = 0; v < 4; v++) acc[u][v] = fmaf(aa[u], bb[v], acc[u][v]);
        }
    }

    // epilogue: scale by reciprocal norms, write tile (coalesced) + staging
    float rn_s[4], rn_t[4];
#pragma unroll
    for (int u = 0; u < 4; u++) rn_s[u] = g_rnorm[b * TLEN + row0 + ty * 4 + u];
#pragma unroll
    for (int v = 0; v < 4; v++) rn_t[v] = g_rnorm[b * TLEN + col0 + tx * 4 + v];

    float* outb = out + (size_t)b * TLEN * TLEN;

    __syncthreads();  // done with As/Bs reads before reusing bandwidth; Cs fresh
#pragma unroll
    for (int u = 0; u < 4; u++) {
        const int s = row0 + ty * 4 + u;
        float v0 = acc[u][0] * rn_s[u] * rn_t[0];
        float v1 = acc[u][1] * rn_s[u] * rn_t[1];
        float v2 = acc[u][2] * rn_s[u] * rn_t[2];
        float v3 = acc[u][3] * rn_s[u] * rn_t[3];
        *(float4*)&outb[(size_t)s * TLEN + col0 + tx * 4] = make_float4(v0, v1, v2, v3);
        Cs[ty * 4 + u][tx * 4 + 0] = v0;
        Cs[ty * 4 + u][tx * 4 + 1] = v1;
        Cs[ty * 4 + u][tx * 4 + 2] = v2;
        Cs[ty * 4 + u][tx * 4 + 3] = v3;
    }
    __syncthreads();

    // transposed tile write: out[t][s], coalesced via staging buffer
    const int tt = tid >> 2;          // 0..63 local t
    const int q  = tid & 3;           // 0..3
#pragma unroll
    for (int it = 0; it < 4; it++) {
        const int sl = it * 16 + q * 4;  // local s base (float4)
        float4 o = make_float4(Cs[sl + 0][tt], Cs[sl + 1][tt],
                               Cs[sl + 2][tt], Cs[sl + 3][tt]);
        *(float4*)&outb[(size_t)(col0 + tt) * TLEN + row0 + sl] = o;
    }
}

extern "C" void kernel_launch(void* const* d_in, const int* in_sizes, int n_in,
                              void* d_out, int out_size) {
    const float* X = (const float*)d_in[0];
    float* out = (float*)d_out;

    norm_kernel<<<BATCH * TLEN, 128>>>(X);

    dim3 grid(NPAIRS, BATCH);
    gemm_kernel<<<grid, 256>>>(X, out);
}

// round 3
// speedup vs baseline: 2.5959x; 2.5959x over previous
#include <cuda_runtime.h>
#include <cuda_bf16.h>
#include <math.h>
#include <stdint.h>

#define BATCH 8
#define TLEN  2048
#define DDIM  512
#define BLK   128
#define BLKK  64
#define NTILE (TLEN / BLK)                  // 16
#define NPAIRS (NTILE * (NTILE + 1) / 2)    // 136
#define NITER (DDIM / BLKK)                 // 8
#define TILE_BYTES 16384                    // 128 rows x 128B
#define STAGE_BYTES (4 * TILE_BYTES)        // Ah, Al, Bh, Bl
#define SMEM_DYN (2 * STAGE_BYTES)          // 128 KB
#define CPAD 132

// normalized rows split into bf16 hi/lo
__device__ __align__(256) __nv_bfloat16 g_H[(size_t)BATCH * TLEN * DDIM];
__device__ __align__(256) __nv_bfloat16 g_L[(size_t)BATCH * TLEN * DDIM];

static __device__ __forceinline__ uint32_t smem_u32(const void* p) {
    uint32_t a;
    asm("{ .reg .u64 t; cvta.to.shared.u64 t, %1; cvt.u32.u64 %0, t; }" : "=r"(a) : "l"(p));
    return a;
}

#define CP_ASYNC16(saddr, gptr) \
    asm volatile("cp.async.cg.shared.global [%0], [%1], 16;" :: "r"(saddr), "l"(gptr))
#define CP_COMMIT() asm volatile("cp.async.commit_group;" ::: "memory")
#define CP_WAIT(n)  asm volatile("cp.async.wait_group %0;" :: "n"(n) : "memory")

#define LDSM4(R, addr) \
    asm volatile("ldmatrix.sync.aligned.m8n8.x4.shared.b16 {%0,%1,%2,%3}, [%4];" \
        : "=r"((R)[0]), "=r"((R)[1]), "=r"((R)[2]), "=r"((R)[3]) : "r"(addr))

#define MMA16816(d, a, b0, b1) \
    asm volatile("mma.sync.aligned.m16n8k16.row.col.f32.bf16.bf16.f32 " \
        "{%0,%1,%2,%3},{%4,%5,%6,%7},{%8,%9},{%0,%1,%2,%3};" \
        : "+f"((d)[0]), "+f"((d)[1]), "+f"((d)[2]), "+f"((d)[3]) \
        : "r"((a)[0]), "r"((a)[1]), "r"((a)[2]), "r"((a)[3]), "r"(b0), "r"(b1))

// ---------------------------------------------------------------------------
// Kernel 1: per-row normalize + bf16 hi/lo split
// ---------------------------------------------------------------------------
__global__ void split_kernel(const float* __restrict__ X) {
    int row = blockIdx.x;
    const float4* xr = (const float4*)(X + (size_t)row * DDIM);
    float4 v = xr[threadIdx.x];  // 128 threads x 4 = 512
    float s = v.x * v.x + v.y * v.y + v.z * v.z + v.w * v.w;
#pragma unroll
    for (int o = 16; o; o >>= 1) s += __shfl_xor_sync(0xffffffffu, s, o);
    __shared__ float ws[4];
    if ((threadIdx.x & 31) == 0) ws[threadIdx.x >> 5] = s;
    __syncthreads();
    float tot = ws[0] + ws[1] + ws[2] + ws[3];
    float rn = 1.0f / fmaxf(sqrtf(tot), 1e-12f);

    float xs[4] = {v.x * rn, v.y * rn, v.z * rn, v.w * rn};
    __nv_bfloat16 h[4], l[4];
#pragma unroll
    for (int u = 0; u < 4; u++) {
        h[u] = __float2bfloat16(xs[u]);
        l[u] = __float2bfloat16(xs[u] - __bfloat162float(h[u]));
    }
    size_t base = (size_t)row * DDIM + threadIdx.x * 4;
    __nv_bfloat162* Hp = (__nv_bfloat162*)(g_H + base);
    __nv_bfloat162* Lp = (__nv_bfloat162*)(g_L + base);
    Hp[0] = __halves2bfloat162(h[0], h[1]);
    Hp[1] = __halves2bfloat162(h[2], h[3]);
    Lp[0] = __halves2bfloat162(l[0], l[1]);
    Lp[1] = __halves2bfloat162(l[2], l[3]);
}

// ---------------------------------------------------------------------------
// Kernel 2: HMMA GEMM  C = H*H^T + H*L^T + L*H^T, triangular + transpose write
// ---------------------------------------------------------------------------
__global__ void __launch_bounds__(512, 1) gemm_kernel(float* __restrict__ out) {
    extern __shared__ __align__(1024) char smem[];
    const uint32_t sbase = smem_u32(smem);

    const int tid  = threadIdx.x;
    const int wid  = tid >> 5;
    const int lane = tid & 31;
    const int b    = blockIdx.y;
    const int lin  = blockIdx.x;

    int j = (int)((sqrtf(8.0f * (float)lin + 1.0f) - 1.0f) * 0.5f);
    while ((j + 1) * (j + 2) / 2 <= lin) j++;
    while (j * (j + 1) / 2 > lin) j--;
    const int i = lin - j * (j + 1) / 2;
    const int row0 = i * BLK;  // s-block
    const int col0 = j * BLK;  // t-block

    const __nv_bfloat16* Hb = g_H + (size_t)b * TLEN * DDIM;
    const __nv_bfloat16* Lb = g_L + (size_t)b * TLEN * DDIM;

    // --- cp.async issue: each thread 2 chunks/tile x 4 tiles ---
    const int c  = tid & 7;       // 16B chunk within 128B row
    const int r0 = tid >> 3;      // 0..63
    // swizzled smem offsets (row-local), stage-independent
    uint32_t soff[2];
#pragma unroll
    for (int q = 0; q < 2; q++) {
        int r = r0 + q * 64;
        soff[q] = (uint32_t)(r * 128 + ((c ^ (r & 7)) << 4));
    }

#define ISSUE(itr, stg) do {                                                   \
        const int kk_ = (itr) * BLKK;                                          \
        const uint32_t st_ = sbase + (stg) * STAGE_BYTES;                      \
        _Pragma("unroll")                                                      \
        for (int q = 0; q < 2; q++) {                                          \
            const int r = r0 + q * 64;                                         \
            const __nv_bfloat16* gA = Hb + (size_t)(row0 + r) * DDIM + kk_ + c * 8; \
            const __nv_bfloat16* gAl = Lb + (size_t)(row0 + r) * DDIM + kk_ + c * 8; \
            const __nv_bfloat16* gB = Hb + (size_t)(col0 + r) * DDIM + kk_ + c * 8; \
            const __nv_bfloat16* gBl = Lb + (size_t)(col0 + r) * DDIM + kk_ + c * 8; \
            CP_ASYNC16(st_ + 0 * TILE_BYTES + soff[q], gA);                    \
            CP_ASYNC16(st_ + 1 * TILE_BYTES + soff[q], gAl);                   \
            CP_ASYNC16(st_ + 2 * TILE_BYTES + soff[q], gB);                    \
            CP_ASYNC16(st_ + 3 * TILE_BYTES + soff[q], gBl);                   \
        }                                                                      \
        CP_COMMIT();                                                           \
    } while (0)

    ISSUE(0, 0);
    ISSUE(1, 1);

    // --- warp tiling: 4(m) x 4(n) warps, 32x32 per warp ---
    const int wm = (wid >> 2) * 32;
    const int wn = (wid & 3) * 32;

    // per-lane ldmatrix row indices (fixed across k)
    const int lrow = lane & 15;         // row within 16-row frag
    const int khalf = (lane >> 4) & 1;  // which 16B half of k16

    float acc[2][4][4];
#pragma unroll
    for (int mf = 0; mf < 2; mf++)
#pragma unroll
        for (int nf = 0; nf < 4; nf++)
#pragma unroll
            for (int u = 0; u < 4; u++) acc[mf][nf][u] = 0.f;

    for (int it = 0; it < NITER; it++) {
        if (it < NITER - 1) CP_WAIT(1); else CP_WAIT(0);
        __syncthreads();

        const uint32_t st = sbase + (it & 1) * STAGE_BYTES;

#pragma unroll
        for (int k2 = 0; k2 < 4; k2++) {
            const int chunk0 = k2 * 2 + khalf;
            uint32_t ah[2][4], al[2][4], bh[2][4], bl[2][4];
#pragma unroll
            for (int mf = 0; mf < 2; mf++) {
                const int row = wm + mf * 16 + lrow;
                const uint32_t off = row * 128 + ((chunk0 ^ (row & 7)) << 4);
                LDSM4(ah[mf], st + 0 * TILE_BYTES + off);
                LDSM4(al[mf], st + 1 * TILE_BYTES + off);
            }
#pragma unroll
            for (int nf2 = 0; nf2 < 2; nf2++) {
                const int row = wn + nf2 * 16 + lrow;
                const uint32_t off = row * 128 + ((chunk0 ^ (row & 7)) << 4);
                LDSM4(bh[nf2], st + 2 * TILE_BYTES + off);
                LDSM4(bl[nf2], st + 3 * TILE_BYTES + off);
            }
#pragma unroll
            for (int mf = 0; mf < 2; mf++)
#pragma unroll
                for (int nf = 0; nf < 4; nf++) {
                    const int g = nf >> 1, o = nf & 1;
                    const uint32_t bh0 = bh[g][o], bh1 = bh[g][o + 2];
                    const uint32_t bl0 = bl[g][o], bl1 = bl[g][o + 2];
                    MMA16816(acc[mf][nf], ah[mf], bh0, bh1);
                    MMA16816(acc[mf][nf], ah[mf], bl0, bl1);
                    MMA16816(acc[mf][nf], al[mf], bh0, bh1);
                }
        }
        __syncthreads();  // all reads done before overwriting this stage
        if (it + 2 < NITER) ISSUE(it + 2, it & 1);
    }

    // --- epilogue: stage C into smem, then dual coalesced writes ---
    float* Cs = (float*)smem;  // [128][CPAD]
#pragma unroll
    for (int mf = 0; mf < 2; mf++)
#pragma unroll
        for (int nf = 0; nf < 4; nf++) {
            const int rr = wm + mf * 16 + (lane >> 2);
            const int cc = wn + nf * 8 + (lane & 3) * 2;
            Cs[rr * CPAD + cc]           = acc[mf][nf][0];
            Cs[rr * CPAD + cc + 1]       = acc[mf][nf][1];
            Cs[(rr + 8) * CPAD + cc]     = acc[mf][nf][2];
            Cs[(rr + 8) * CPAD + cc + 1] = acc[mf][nf][3];
        }
    __syncthreads();

    float* outb = out + (size_t)b * TLEN * TLEN;

    // direct tile: out[row0+r][col0 .. col0+127]; warp w covers rows w, w+16,...
#pragma unroll
    for (int k = 0; k < 8; k++) {
        const int r = wid + k * 16;
        const float* src = Cs + r * CPAD + lane * 4;
        *(float4*)(outb + (size_t)(row0 + r) * TLEN + col0 + lane * 4) =
            make_float4(src[0], src[1], src[2], src[3]);
    }
    // transposed tile: out[col0+t][row0 .. row0+127]
    if (i != j) {
#pragma unroll
        for (int k = 0; k < 8; k++) {
            const int t = wid + k * 16;
            const int s = lane * 4;
            *(float4*)(outb + (size_t)(col0 + t) * TLEN + row0 + s) =
                make_float4(Cs[(s + 0) * CPAD + t], Cs[(s + 1) * CPAD + t],
                            Cs[(s + 2) * CPAD + t], Cs[(s + 3) * CPAD + t]);
        }
    }
}

extern "C" void kernel_launch(void* const* d_in, const int* in_sizes, int n_in,
                              void* d_out, int out_size) {
    const float* X = (const float*)d_in[0];
    float* out = (float*)d_out;

    split_kernel<<<BATCH * TLEN, 128>>>(X);

    static int cfg_done = 0;
    if (!cfg_done) {
        cudaFuncSetAttribute(gemm_kernel, cudaFuncAttributeMaxDynamicSharedMemorySize, SMEM_DYN);
        cfg_done = 1;
    }
    dim3 grid(NPAIRS, BATCH);
    gemm_kernel<<<grid, 512, SMEM_DYN>>>(out);
}

// round 4
// speedup vs baseline: 2.8548x; 1.0998x over previous
#include <cuda_runtime.h>
#include <cuda_bf16.h>
#include <math.h>
#include <stdint.h>

#define BATCH 8
#define TLEN  2048
#define DDIM  512
#define BLK   128
#define BLKK  32
#define NTILE (TLEN / BLK)                  // 16
#define NPAIRS (NTILE * (NTILE + 1) / 2)    // 136
#define NITER (DDIM / BLKK)                 // 16
#define TB    8192                          // one operand tile: 128 rows x 64B
#define STAGE_BYTES (4 * TB)                // Ah, Al, Bh, Bl = 32KB
#define NSTAGE 3
#define SMEM_DYN (NSTAGE * STAGE_BYTES)     // 96KB
#define CPAD 129

__device__ __align__(256) __nv_bfloat16 g_H[(size_t)BATCH * TLEN * DDIM];
__device__ __align__(256) __nv_bfloat16 g_L[(size_t)BATCH * TLEN * DDIM];

static __device__ __forceinline__ uint32_t smem_u32(const void* p) {
    uint32_t a;
    asm("{ .reg .u64 t; cvta.to.shared.u64 t, %1; cvt.u32.u64 %0, t; }" : "=r"(a) : "l"(p));
    return a;
}

#define CP_ASYNC16(saddr, gptr) \
    asm volatile("cp.async.cg.shared.global [%0], [%1], 16;" :: "r"(saddr), "l"(gptr))
#define CP_COMMIT() asm volatile("cp.async.commit_group;" ::: "memory")
#define CP_WAIT(n)  asm volatile("cp.async.wait_group %0;" :: "n"(n) : "memory")

#define LDSM4(R, addr) \
    asm volatile("ldmatrix.sync.aligned.m8n8.x4.shared.b16 {%0,%1,%2,%3}, [%4];" \
        : "=r"((R)[0]), "=r"((R)[1]), "=r"((R)[2]), "=r"((R)[3]) : "r"(addr))

#define MMA16816(d, a, b0, b1) \
    asm volatile("mma.sync.aligned.m16n8k16.row.col.f32.bf16.bf16.f32 " \
        "{%0,%1,%2,%3},{%4,%5,%6,%7},{%8,%9},{%0,%1,%2,%3};" \
        : "+f"((d)[0]), "+f"((d)[1]), "+f"((d)[2]), "+f"((d)[3]) \
        : "r"((a)[0]), "r"((a)[1]), "r"((a)[2]), "r"((a)[3]), "r"(b0), "r"(b1))

// ---------------------------------------------------------------------------
// Kernel 1: per-row normalize + bf16 hi/lo split
// ---------------------------------------------------------------------------
__global__ void split_kernel(const float* __restrict__ X) {
    int row = blockIdx.x;
    const float4* xr = (const float4*)(X + (size_t)row * DDIM);
    float4 v = xr[threadIdx.x];  // 128 threads x 4 = 512
    float s = v.x * v.x + v.y * v.y + v.z * v.z + v.w * v.w;
#pragma unroll
    for (int o = 16; o; o >>= 1) s += __shfl_xor_sync(0xffffffffu, s, o);
    __shared__ float ws[4];
    if ((threadIdx.x & 31) == 0) ws[threadIdx.x >> 5] = s;
    __syncthreads();
    float tot = ws[0] + ws[1] + ws[2] + ws[3];
    float rn = 1.0f / fmaxf(sqrtf(tot), 1e-12f);

    float xs[4] = {v.x * rn, v.y * rn, v.z * rn, v.w * rn};
    __nv_bfloat16 h[4], l[4];
#pragma unroll
    for (int u = 0; u < 4; u++) {
        h[u] = __float2bfloat16(xs[u]);
        l[u] = __float2bfloat16(xs[u] - __bfloat162float(h[u]));
    }
    size_t base = (size_t)row * DDIM + threadIdx.x * 4;
    __nv_bfloat162* Hp = (__nv_bfloat162*)(g_H + base);
    __nv_bfloat162* Lp = (__nv_bfloat162*)(g_L + base);
    Hp[0] = __halves2bfloat162(h[0], h[1]);
    Hp[1] = __halves2bfloat162(h[2], h[3]);
    Lp[0] = __halves2bfloat162(l[0], l[1]);
    Lp[1] = __halves2bfloat162(l[2], l[3]);
}

// ---------------------------------------------------------------------------
// Kernel 2: HMMA GEMM  C = H H^T + H L^T + L H^T
// 128 threads, 4 warps of 64x64; 3-stage cp.async; 2 CTAs/SM
// ---------------------------------------------------------------------------
__global__ void __launch_bounds__(128, 2) gemm_kernel(float* __restrict__ out) {
    extern __shared__ __align__(1024) char smem[];
    const uint32_t sbase = smem_u32(smem);

    const int tid  = threadIdx.x;
    const int wid  = tid >> 5;
    const int lane = tid & 31;
    const int b    = blockIdx.y;
    const int lin  = blockIdx.x;

    int j = (int)((sqrtf(8.0f * (float)lin + 1.0f) - 1.0f) * 0.5f);
    while ((j + 1) * (j + 2) / 2 <= lin) j++;
    while (j * (j + 1) / 2 > lin) j--;
    const int i = lin - j * (j + 1) / 2;
    const int row0 = i * BLK;
    const int col0 = j * BLK;

    const __nv_bfloat16* Hb = g_H + (size_t)b * TLEN * DDIM;
    const __nv_bfloat16* Lb = g_L + (size_t)b * TLEN * DDIM;

    // cp.async mapping: thread -> (row r, 16B chunk c); 4 row-passes per tile
    const int c  = tid & 3;
    const int r0 = tid >> 2;  // 0..31

#define ISSUE(itr) do {                                                        \
        const int kk_ = (itr) * BLKK;                                          \
        const uint32_t st_ = sbase + ((itr) % NSTAGE) * STAGE_BYTES;           \
        _Pragma("unroll")                                                      \
        for (int q = 0; q < 4; q++) {                                          \
            const int r = r0 + q * 32;                                         \
            const uint32_t so = (uint32_t)(r * 64 + ((c ^ ((r >> 1) & 3)) << 4)); \
            const size_t ga = (size_t)(row0 + r) * DDIM + kk_ + c * 8;         \
            const size_t gb = (size_t)(col0 + r) * DDIM + kk_ + c * 8;         \
            CP_ASYNC16(st_ + 0 * TB + so, Hb + ga);                            \
            CP_ASYNC16(st_ + 1 * TB + so, Lb + ga);                            \
            CP_ASYNC16(st_ + 2 * TB + so, Hb + gb);                            \
            CP_ASYNC16(st_ + 3 * TB + so, Lb + gb);                            \
        }                                                                      \
        CP_COMMIT();                                                           \
    } while (0)

    ISSUE(0); ISSUE(1); ISSUE(2);

    // warp quadrant: 2x2 grid of 64x64
    const int wm = (wid >> 1) * 64;
    const int wn = (wid & 1) * 64;
    const int lrow  = lane & 15;
    const int khalf = lane >> 4;

    float acc[4][8][4];
#pragma unroll
    for (int mf = 0; mf < 4; mf++)
#pragma unroll
        for (int nf = 0; nf < 8; nf++)
#pragma unroll
            for (int u = 0; u < 4; u++) acc[mf][nf][u] = 0.f;

    for (int it = 0; it < NITER; it++) {
        CP_WAIT(2);
        __syncthreads();
        const uint32_t st = sbase + (it % NSTAGE) * STAGE_BYTES;

#pragma unroll
        for (int kk2 = 0; kk2 < 2; kk2++) {
            const int chunk0 = kk2 * 2 + khalf;
            uint32_t ah[4][4], al[4][4], bx[4][4];
#pragma unroll
            for (int mf = 0; mf < 4; mf++) {
                const int row = wm + mf * 16 + lrow;
                const uint32_t off = row * 64 + ((chunk0 ^ ((row >> 1) & 3)) << 4);
                LDSM4(ah[mf], st + 0 * TB + off);
                LDSM4(al[mf], st + 1 * TB + off);
            }
            // B-hi: terms H*H^T and L*H^T
#pragma unroll
            for (int g = 0; g < 4; g++) {
                const int row = wn + g * 16 + lrow;
                const uint32_t off = row * 64 + ((chunk0 ^ ((row >> 1) & 3)) << 4);
                LDSM4(bx[g], st + 2 * TB + off);
            }
#pragma unroll
            for (int mf = 0; mf < 4; mf++)
#pragma unroll
                for (int nf = 0; nf < 8; nf++) {
                    const int g = nf >> 1, o = nf & 1;
                    MMA16816(acc[mf][nf], ah[mf], bx[g][o], bx[g][o + 2]);
                    MMA16816(acc[mf][nf], al[mf], bx[g][o], bx[g][o + 2]);
                }
            // B-lo: term H*L^T
#pragma unroll
            for (int g = 0; g < 4; g++) {
                const int row = wn + g * 16 + lrow;
                const uint32_t off = row * 64 + ((chunk0 ^ ((row >> 1) & 3)) << 4);
                LDSM4(bx[g], st + 3 * TB + off);
            }
#pragma unroll
            for (int mf = 0; mf < 4; mf++)
#pragma unroll
                for (int nf = 0; nf < 8; nf++) {
                    const int g = nf >> 1, o = nf & 1;
                    MMA16816(acc[mf][nf], ah[mf], bx[g][o], bx[g][o + 2]);
                }
        }
        __syncthreads();
        if (it + NSTAGE < NITER) ISSUE(it + NSTAGE); else CP_COMMIT();
    }

    // --- epilogue: stage into smem, dual coalesced writes ---
    float* Cs = (float*)smem;  // [128][CPAD]
#pragma unroll
    for (int mf = 0; mf < 4; mf++)
#pragma unroll
        for (int nf = 0; nf < 8; nf++) {
            const int rr = wm + mf * 16 + (lane >> 2);
            const int cc = wn + nf * 8 + (lane & 3) * 2;
            Cs[rr * CPAD + cc]           = acc[mf][nf][0];
            Cs[rr * CPAD + cc + 1]       = acc[mf][nf][1];
            Cs[(rr + 8) * CPAD + cc]     = acc[mf][nf][2];
            Cs[(rr + 8) * CPAD + cc + 1] = acc[mf][nf][3];
        }
    __syncthreads();

    float* outb = out + (size_t)b * TLEN * TLEN;

    // direct tile: warp w rows [w*32, w*32+32)
#pragma unroll
    for (int k = 0; k < 32; k++) {
        const int r = wid * 32 + k;
        const float* src = Cs + r * CPAD + lane * 4;
        *(float4*)(outb + (size_t)(row0 + r) * TLEN + col0 + lane * 4) =
            make_float4(src[0], src[1], src[2], src[3]);
    }
    // transposed tile
    if (i != j) {
#pragma unroll
        for (int tk = 0; tk < 32; tk++) {
            const int t = wid * 32 + tk;
            const int s = lane * 4;
            *(float4*)(outb + (size_t)(col0 + t) * TLEN + row0 + s) =
                make_float4(Cs[(s + 0) * CPAD + t], Cs[(s + 1) * CPAD + t],
                            Cs[(s + 2) * CPAD + t], Cs[(s + 3) * CPAD + t]);
        }
    }
}

extern "C" void kernel_launch(void* const* d_in, const int* in_sizes, int n_in,
                              void* d_out, int out_size) {
    const float* X = (const float*)d_in[0];
    float* out = (float*)d_out;

    split_kernel<<<BATCH * TLEN, 128>>>(X);

    static int cfg_done = 0;
    if (!cfg_done) {
        cudaFuncSetAttribute(gemm_kernel, cudaFuncAttributeMaxDynamicSharedMemorySize, SMEM_DYN);
        cfg_done = 1;
    }
    dim3 grid(NPAIRS, BATCH);
    gemm_kernel<<<grid, 128, SMEM_DYN>>>(out);
}